// round 7
// baseline (speedup 1.0000x reference)
#include <cuda_runtime.h>
#include <cuda_bf16.h>
#include <math.h>
#include <stdint.h>

#define BATCH 512
#define SEQ   196
#define HID   1024
#define MID   512
#define FOUT  2048
#define NB    100
#define ROWS  (BATCH*SEQ)      // 100352

__device__ __align__(16) float g_att[ROWS];
__device__ __align__(16) float g_ctx[BATCH*HID];
__device__ __align__(16) __nv_bfloat16 g_w1b[MID*HID];

__device__ __forceinline__ unsigned pack_bf16(float lo, float hi) {
    unsigned r; asm("cvt.rn.bf16x2.f32 %0, %1, %2;" : "=r"(r) : "f"(hi), "f"(lo)); return r;
}
__device__ __forceinline__ unsigned f2tf32(float x) {
    unsigned y; asm("cvt.rna.tf32.f32 %0, %1;" : "=r"(y) : "f"(x)); return y;
}
__device__ __forceinline__ uint32_t smem_u32(const void* p) {
    uint32_t a;
    asm("{ .reg .u64 t; cvta.to.shared.u64 t, %1; cvt.u32.u64 %0, t; }" : "=r"(a) : "l"(p));
    return a;
}

#define SWZ64(o) ((o) ^ (((o) >> 3) & 0x30))
#define CP16(dst, src) \
    asm volatile("cp.async.cg.shared.global [%0], [%1], 16;" :: "r"(dst), "l"(src) : "memory")
#define CP_COMMIT() asm volatile("cp.async.commit_group;" ::: "memory")
#define CP_WAIT2()  asm volatile("cp.async.wait_group 2;" ::: "memory")
#define STS128U(addr, r0, r1, r2, r3) \
    asm volatile("st.shared.v4.b32 [%0], {%1,%2,%3,%4};" \
                 :: "r"(addr), "r"(r0), "r"(r1), "r"(r2), "r"(r3) : "memory")
#define LDSM_X4(r0, r1, r2, r3, addr) \
    asm volatile("ldmatrix.sync.aligned.m8n8.x4.shared.b16 {%0,%1,%2,%3}, [%4];" \
                 : "=r"(r0), "=r"(r1), "=r"(r2), "=r"(r3) : "r"(addr))
#define MMA_BF16(d, a0, a1, a2, a3, b0, b1) \
    asm volatile("mma.sync.aligned.m16n8k16.row.col.f32.bf16.bf16.f32 " \
                 "{%0,%1,%2,%3},{%4,%5,%6,%7},{%8,%9},{%0,%1,%2,%3};" \
                 : "+f"((d)[0]), "+f"((d)[1]), "+f"((d)[2]), "+f"((d)[3]) \
                 : "r"(a0), "r"(a1), "r"(a2), "r"(a3), "r"(b0), "r"(b1))

// ===========================================================================
// k_pre: cvt W1 -> bf16 (1MB), zero g_att
// ===========================================================================
__global__ void k_pre(const float* __restrict__ W1) {
    size_t i = (size_t)blockIdx.x * 256 + threadIdx.x;
    if (i < 131072) {
        float4 v = ((const float4*)W1)[i];
        ((uint2*)g_w1b)[i] = make_uint2(pack_bf16(v.x, v.y), pack_bf16(v.z, v.w));
    } else {
        ((float4*)g_att)[i - 131072] = make_float4(0.f, 0.f, 0.f, 0.f);
    }
}

// ===========================================================================
// k_mlp_att: bf16 mma.sync GEMM. BM=128, BN=128, BK=32.
//   128 threads = 4 warps of 64x64 tiles (128 B smem / MMA). 2 CTAs/SM.
//   A (x fp32): LDG -> cvt -> STS, double-buffered.
//   B (W1 bf16): 4-stage cp.async ring, stage issued after the barrier.
//   Fused relu/W2 row-sum epilogue -> atomicAdd g_att.
// ===========================================================================
#define NKT 32
#define OFF_A(s)  ((s) * 8192)                  // 128 rows * 64B, 2 stages
#define OFF_B(s)  (16384 + (s) * 8192)          // 128 rows * 64B, 4 stages
#define OFF_SC    49152
#define GEMM_SMEM (OFF_SC + 1536)

__global__ __launch_bounds__(128, 2)
void k_mlp_att(const float* __restrict__ x,
               const float* __restrict__ b1,
               const float* __restrict__ W2) {
    extern __shared__ __align__(1024) char smem[];
    const uint32_t sbase = smem_u32(smem);

    const int tid  = threadIdx.x;
    const int lane = tid & 31;
    const int warp = tid >> 5;
    const int colBase = blockIdx.x * 128;     // 4 n tiles (fastest)
    const int rowBase = blockIdx.y * 128;

    float* b1s    = (float*)(smem + OFF_SC);
    float* w2s    = (float*)(smem + OFF_SC + 512);
    float* s_part = (float*)(smem + OFF_SC + 1024);

    b1s[tid] = b1[colBase + tid];
    w2s[tid] = W2[colBase + tid];
    s_part[tid] = 0.f;

    // 2x2 warps, 64x64 tiles
    const int wm = warp & 1, wn = warp >> 1;
    const int mBase = wm * 64, nBase = wn * 64;
    const int g = lane >> 2, t = lane & 3;

    const int aRow = mBase + (lane & 15);
    const int aKb  = (lane >> 4) * 16;
    const int bRow = nBase + (lane & 7) + ((lane >> 4) * 8);
    const int bKb  = ((lane >> 3) & 1) * 16;

    uint32_t aOff[4][2], bOff[4][2];
    #pragma unroll
    for (int mi = 0; mi < 4; mi++)
        #pragma unroll
        for (int ks = 0; ks < 2; ks++)
            aOff[mi][ks] = SWZ64((uint32_t)((aRow + mi * 16) * 64 + ks * 32 + aKb));
    #pragma unroll
    for (int nj = 0; nj < 4; nj++)
        #pragma unroll
        for (int ks = 0; ks < 2; ks++)
            bOff[nj][ks] = SWZ64((uint32_t)((bRow + nj * 16) * 64 + ks * 32 + bKb));

    // A staging: one full row per thread (row = tid), 32 floats per kt
    const float* aSrc = x + (size_t)(rowBase + tid) * HID;
    uint32_t aDst[4];
    #pragma unroll
    for (int c = 0; c < 4; c++) aDst[c] = SWZ64((uint32_t)(tid * 64 + c * 16));

    // B cp.async: one row per thread (row = tid), 4x16B per kt
    const __nv_bfloat16* bSrc = g_w1b + (size_t)(colBase + tid) * HID;

    float acc[4][8][4];
    #pragma unroll
    for (int mi = 0; mi < 4; mi++)
        #pragma unroll
        for (int ni = 0; ni < 8; ni++)
            #pragma unroll
            for (int q = 0; q < 4; q++) acc[mi][ni][q] = 0.f;

    // ---- prologue: B stages 0..2, A stage 0 ----
    #pragma unroll
    for (int s = 0; s < 3; ++s) {
        const uint32_t bb = sbase + OFF_B(s);
        #pragma unroll
        for (int c = 0; c < 4; c++) CP16(bb + aDst[c], bSrc + s * 32 + c * 8);
        CP_COMMIT();
    }
    {
        float4 f[8];
        #pragma unroll
        for (int c = 0; c < 8; c++) f[c] = *(const float4*)(aSrc + c * 4);
        #pragma unroll
        for (int c = 0; c < 4; c++)
            STS128U(sbase + OFF_A(0) + aDst[c],
                    pack_bf16(f[2*c].x, f[2*c].y),   pack_bf16(f[2*c].z, f[2*c].w),
                    pack_bf16(f[2*c+1].x, f[2*c+1].y), pack_bf16(f[2*c+1].z, f[2*c+1].w));
    }

    for (int kt = 0; kt < NKT; ++kt) {
        // issue next A loads early (used after next barrier)
        float4 f[8];
        if (kt < NKT - 1) {
            const float* p = aSrc + (kt + 1) * 32;
            #pragma unroll
            for (int c = 0; c < 8; c++) f[c] = *(const float4*)(p + c * 4);
        }

        CP_WAIT2();            // B stage kt resident (2 younger groups in flight)
        __syncthreads();       // A[kt&1], B[kt&3] visible; prior stage reads done

        if (kt + 3 < NKT) {
            const uint32_t bb = sbase + OFF_B((kt + 3) & 3);
            #pragma unroll
            for (int c = 0; c < 4; c++) CP16(bb + aDst[c], bSrc + (kt + 3) * 32 + c * 8);
        }
        CP_COMMIT();

        const uint32_t aBase = sbase + OFF_A(kt & 1);
        const uint32_t bBase = sbase + OFF_B(kt & 3);
        #pragma unroll
        for (int ks = 0; ks < 2; ++ks) {
            uint32_t a[4][4];
            #pragma unroll
            for (int mi = 0; mi < 4; mi++)
                LDSM_X4(a[mi][0], a[mi][1], a[mi][2], a[mi][3], aBase + aOff[mi][ks]);
            #pragma unroll
            for (int nj = 0; nj < 4; nj++) {
                uint32_t b0, b1r, b2, b3;
                LDSM_X4(b0, b1r, b2, b3, bBase + bOff[nj][ks]);
                #pragma unroll
                for (int mi = 0; mi < 4; mi++) {
                    MMA_BF16(acc[mi][nj * 2],     a[mi][0], a[mi][1], a[mi][2], a[mi][3], b0, b1r);
                    MMA_BF16(acc[mi][nj * 2 + 1], a[mi][0], a[mi][1], a[mi][2], a[mi][3], b2, b3);
                }
            }
        }

        if (kt < NKT - 1) {
            const uint32_t ab = sbase + OFF_A((kt + 1) & 1);
            #pragma unroll
            for (int c = 0; c < 4; c++)
                STS128U(ab + aDst[c],
                        pack_bf16(f[2*c].x, f[2*c].y),     pack_bf16(f[2*c].z, f[2*c].w),
                        pack_bf16(f[2*c+1].x, f[2*c+1].y), pack_bf16(f[2*c+1].z, f[2*c+1].w));
        }
    }

    // epilogue: relu(acc+b1)*W2 row-sum over this CTA's 128 cols
    #pragma unroll
    for (int mi = 0; mi < 4; mi++) {
        float s0 = 0.f, s1 = 0.f;
        #pragma unroll
        for (int ni = 0; ni < 8; ni++) {
            int c = nBase + ni * 8 + t * 2;
            s0 += fmaxf(acc[mi][ni][0] + b1s[c],     0.f) * w2s[c]
                + fmaxf(acc[mi][ni][1] + b1s[c + 1], 0.f) * w2s[c + 1];
            s1 += fmaxf(acc[mi][ni][2] + b1s[c],     0.f) * w2s[c]
                + fmaxf(acc[mi][ni][3] + b1s[c + 1], 0.f) * w2s[c + 1];
        }
        s0 += __shfl_xor_sync(0xffffffff, s0, 1); s0 += __shfl_xor_sync(0xffffffff, s0, 2);
        s1 += __shfl_xor_sync(0xffffffff, s1, 1); s1 += __shfl_xor_sync(0xffffffff, s1, 2);
        if (t == 0) {
            atomicAdd(&s_part[mBase + mi * 16 + g],     s0);
            atomicAdd(&s_part[mBase + mi * 16 + 8 + g], s1);
        }
    }
    __syncthreads();
    atomicAdd(&g_att[rowBase + tid], s_part[tid]);
}

// ===========================================================================
// k_stats4: per-batch softmax/moments/r/w, then h-sliced context stream.
// ===========================================================================
__global__ __launch_bounds__(256)
void k_stats4(const float* __restrict__ x,
              const unsigned char* __restrict__ mask,
              const float* __restrict__ G,
              const float* __restrict__ mub) {
    __shared__ float smax[8], ssum[8][6];
    __shared__ float r_s[NB], w_s[SEQ];
    __shared__ float4 red[256];

    const int b = blockIdx.y, slice = blockIdx.x;
    const int tid = threadIdx.x, lane = tid & 31, warp = tid >> 5;

    float logit = -3.0e38f;
    if (tid < SEQ) {
        logit = g_att[b * SEQ + tid];
        if (mask[b * SEQ + tid]) logit = -1.0e9f;
    }
    float v = logit;
    #pragma unroll
    for (int off = 16; off > 0; off >>= 1) v = fmaxf(v, __shfl_xor_sync(0xffffffff, v, off));
    if (lane == 0) smax[warp] = v;
    __syncthreads();
    float mx = smax[0];
    #pragma unroll
    for (int w = 1; w < 8; w++) mx = fmaxf(mx, smax[w]);

    float e = (tid < SEQ) ? expf(logit - mx) : 0.f;
    float px = 0.f, py = 0.f;
    if (tid < SEQ) { px = (float)(tid / 14) * (1.f / 13.f); py = (float)(tid % 14) * (1.f / 13.f); }
    float s6[6] = { e, e * px, e * py, e * px * px, e * px * py, e * py * py };
    #pragma unroll
    for (int q = 0; q < 6; q++) {
        float sv = s6[q];
        #pragma unroll
        for (int off = 16; off > 0; off >>= 1) sv += __shfl_xor_sync(0xffffffff, sv, off);
        if (lane == 0) ssum[warp][q] = sv;
    }
    __syncthreads();
    float sums[6];
    #pragma unroll
    for (int q = 0; q < 6; q++) {
        float sv = 0.f;
        #pragma unroll
        for (int w = 0; w < 8; w++) sv += ssum[w][q];
        sums[q] = sv;
    }

    const float S   = sums[0];
    const float Mux = sums[1] / S, Muy = sums[2] / S;
    float S00 = sums[3] / S - Mux * Mux + 1e-6f;
    float S01 = sums[4] / S - Mux * Muy;
    float S11 = sums[5] / S - Muy * Muy + 1e-6f;
    float det = S00 * S11 - S01 * S01;
    float I00 = S11 / det, I01 = -S01 / det, I11 = S00 / det;
    float t0 = I00 * Mux + I01 * Muy;
    float t1 = I01 * Mux + I11 * Muy;
    float ds = I00 * I11 - I01 * I01;
    float R00 = I11 / ds, R01 = -I01 / ds, R11 = I00 / ds;
    float m0 = R00 * t0 + R01 * t1;
    float m1 = R01 * t0 + R11 * t1;
    float A00 = R00 + 1e-3f, A01 = R01, A11 = R11 + 1e-3f;
    float detA = A00 * A11 - A01 * A01;
    float Ai00 = A11 / detA, Ai01 = -A01 / detA, Ai11 = A00 / detA;
    float coef = 1.f / (6.2831853071795864769f * sqrtf(detA));

    if (tid < NB) {
        float d0 = m0 - mub[2 * tid];
        float d1 = m1 - mub[2 * tid + 1];
        float quad = d0 * (Ai00 * d0 + Ai01 * d1) + d1 * (Ai01 * d0 + Ai11 * d1);
        r_s[tid] = expf(-0.5f * quad) * coef;
    }
    __syncthreads();
    if (tid < SEQ) {
        float wv = 0.f;
        #pragma unroll 4
        for (int k = 0; k < NB; k++) wv += G[tid * NB + k] * r_s[k];
        w_s[tid] = wv;
    }
    __syncthreads();

    const int h4 = tid & 63, nn = tid >> 6;
    const float4* xb = (const float4*)(x + (size_t)b * SEQ * HID) + slice * 64 + h4;
    float ax = 0.f, ay = 0.f, az = 0.f, aw = 0.f;
    #pragma unroll 7
    for (int n = nn; n < SEQ; n += 4) {
        float4 vv = xb[n * 256];
        float wv = w_s[n];
        ax += wv * vv.x; ay += wv * vv.y; az += wv * vv.z; aw += wv * vv.w;
    }
    red[tid] = make_float4(ax, ay, az, aw);
    __syncthreads();
    if (tid < 64) {
        float4 a0 = red[tid], a1 = red[tid + 64], a2 = red[tid + 128], a3 = red[tid + 192];
        float4 o;
        o.x = a0.x + a1.x + a2.x + a3.x;
        o.y = a0.y + a1.y + a2.y + a3.y;
        o.z = a0.z + a1.z + a2.z + a3.z;
        o.w = a0.w + a1.w + a2.w + a3.w;
        ((float4*)(g_ctx + (size_t)b * HID + slice * 256))[tid] = o;
    }
}

// ===========================================================================
// k_out2: out = ctx(512x1024) @ Wm^T + bm  (tf32 mma.sync)
//   BM=32, BN=128 -> grid (16,16) = 256 CTAs (was 128: grid-limited)
// ===========================================================================
#define BM2 32
#define BN2 128
#define XS2 20

__global__ __launch_bounds__(256, 2)
void k_out2(const float* __restrict__ Wm, const float* __restrict__ bm,
            float* __restrict__ out) {
    __shared__ unsigned sa[2][BM2][XS2];
    __shared__ unsigned sbm[2][BN2][XS2];

    const int tid = threadIdx.x;
    const int mB = blockIdx.x * BM2, nB = blockIdx.y * BN2;
    const int lr = tid >> 2, lc = (tid & 3) * 4;     // lr 0..63
    const int warp = tid >> 5, lane = tid & 31;
    const int wm = warp & 1, wn = warp >> 1;
    const int mBase = wm * 16, nBase = wn * 32;
    const int g = lane >> 2, t = lane & 3;

    float acc[4][4];
    #pragma unroll
    for (int ni = 0; ni < 4; ni++)
        #pragma unroll
        for (int q = 0; q < 4; q++) acc[ni][q] = 0.f;

    float4 pa, pb0, pb1;
    if (lr < BM2) pa = *(const float4*)&g_ctx[(size_t)(mB + lr) * HID + lc];
    pb0 = *(const float4*)&Wm[(size_t)(nB + lr) * HID + lc];
    pb1 = *(const float4*)&Wm[(size_t)(nB + lr + 64) * HID + lc];
    if (lr < BM2) {
        sa[0][lr][lc+0] = f2tf32(pa.x); sa[0][lr][lc+1] = f2tf32(pa.y);
        sa[0][lr][lc+2] = f2tf32(pa.z); sa[0][lr][lc+3] = f2tf32(pa.w);
    }
    sbm[0][lr][lc+0] = f2tf32(pb0.x); sbm[0][lr][lc+1] = f2tf32(pb0.y);
    sbm[0][lr][lc+2] = f2tf32(pb0.z); sbm[0][lr][lc+3] = f2tf32(pb0.w);
    sbm[0][lr+64][lc+0] = f2tf32(pb1.x); sbm[0][lr+64][lc+1] = f2tf32(pb1.y);
    sbm[0][lr+64][lc+2] = f2tf32(pb1.z); sbm[0][lr+64][lc+3] = f2tf32(pb1.w);
    __syncthreads();

    const int NT = HID / 16;
    for (int kt = 0; kt < NT; ++kt) {
        const int buf = kt & 1;
        if (kt < NT - 1) {
            int k0 = (kt + 1) * 16;
            if (lr < BM2) pa = *(const float4*)&g_ctx[(size_t)(mB + lr) * HID + k0 + lc];
            pb0 = *(const float4*)&Wm[(size_t)(nB + lr) * HID + k0 + lc];
            pb1 = *(const float4*)&Wm[(size_t)(nB + lr + 64) * HID + k0 + lc];
        }
        #pragma unroll
        for (int ks = 0; ks < 2; ++ks) {
            const int k0s = ks * 8;
            unsigned a[4], bf[4][2];
            {
                int r0 = mBase + g;
                a[0] = sa[buf][r0    ][k0s + t];
                a[1] = sa[buf][r0 + 8][k0s + t];
                a[2] = sa[buf][r0    ][k0s + t + 4];
                a[3] = sa[buf][r0 + 8][k0s + t + 4];
            }
            #pragma unroll
            for (int ni = 0; ni < 4; ni++) {
                int c0 = nBase + ni * 8 + g;
                bf[ni][0] = sbm[buf][c0][k0s + t];
                bf[ni][1] = sbm[buf][c0][k0s + t + 4];
            }
            #pragma unroll
            for (int ni = 0; ni < 4; ni++)
                asm volatile(
                    "mma.sync.aligned.m16n8k8.row.col.f32.tf32.tf32.f32 "
                    "{%0,%1,%2,%3},{%4,%5,%6,%7},{%8,%9},{%0,%1,%2,%3};"
                    : "+f"(acc[ni][0]), "+f"(acc[ni][1]),
                      "+f"(acc[ni][2]), "+f"(acc[ni][3])
                    : "r"(a[0]), "r"(a[1]), "r"(a[2]), "r"(a[3]),
                      "r"(bf[ni][0]), "r"(bf[ni][1]));
        }
        if (kt < NT - 1) {
            int nb = buf ^ 1;
            if (lr < BM2) {
                sa[nb][lr][lc+0] = f2tf32(pa.x); sa[nb][lr][lc+1] = f2tf32(pa.y);
                sa[nb][lr][lc+2] = f2tf32(pa.z); sa[nb][lr][lc+3] = f2tf32(pa.w);
            }
            sbm[nb][lr][lc+0] = f2tf32(pb0.x); sbm[nb][lr][lc+1] = f2tf32(pb0.y);
            sbm[nb][lr][lc+2] = f2tf32(pb0.z); sbm[nb][lr][lc+3] = f2tf32(pb0.w);
            sbm[nb][lr+64][lc+0] = f2tf32(pb1.x); sbm[nb][lr+64][lc+1] = f2tf32(pb1.y);
            sbm[nb][lr+64][lc+2] = f2tf32(pb1.z); sbm[nb][lr+64][lc+3] = f2tf32(pb1.w);
        }
        __syncthreads();
    }

    #pragma unroll
    for (int ni = 0; ni < 4; ni++) {
        int r0 = mB + mBase + g;
        int c0 = nB + nBase + ni * 8 + t * 2;
        float bm0 = bm[c0], bm1 = bm[c0 + 1];
        out[(size_t)r0 * FOUT + c0]           = acc[ni][0] + bm0;
        out[(size_t)r0 * FOUT + c0 + 1]       = acc[ni][1] + bm1;
        out[(size_t)(r0 + 8) * FOUT + c0]     = acc[ni][2] + bm0;
        out[(size_t)(r0 + 8) * FOUT + c0 + 1] = acc[ni][3] + bm1;
    }
}

// ---------------------------------------------------------------------------
extern "C" void kernel_launch(void* const* d_in, const int* in_sizes, int n_in,
                              void* d_out, int out_size) {
    const float*         x   = (const float*)d_in[0];
    const unsigned char* xm  = (const unsigned char*)d_in[1];
    const float*         W1  = (const float*)d_in[2];
    const float*         b1  = (const float*)d_in[3];
    const float*         W2  = (const float*)d_in[4];
    // d_in[5] = b2: softmax-invariant
    const float*         Wm  = (const float*)d_in[6];
    const float*         bm  = (const float*)d_in[7];
    const float*         G   = (const float*)d_in[8];
    const float*         mub = (const float*)d_in[9];
    float* out = (float*)d_out;

    cudaFuncSetAttribute(k_mlp_att, cudaFuncAttributeMaxDynamicSharedMemorySize, GEMM_SMEM);

    k_pre<<<610, 256>>>(W1);
    k_mlp_att<<<dim3(4, ROWS / 128), 128, GEMM_SMEM>>>(x, b1, W2);
    k_stats4<<<dim3(4, BATCH), 256>>>(x, xm, G, mub);
    k_out2<<<dim3(BATCH / BM2, FOUT / BN2), 256>>>(Wm, bm, out);
}

// round 8
// speedup vs baseline: 1.3125x; 1.3125x over previous
#include <cuda_runtime.h>
#include <cuda_bf16.h>
#include <math.h>
#include <stdint.h>

#define BATCH 512
#define SEQ   196
#define HID   1024
#define MID   512
#define FOUT  2048
#define NB    100
#define ROWS  (BATCH*SEQ)      // 100352

__device__ __align__(16) float g_att[ROWS];
__device__ __align__(16) float g_ctx[BATCH*HID];
__device__ __align__(16) __nv_bfloat16 g_w1b[MID*HID];

__device__ __forceinline__ unsigned pack_bf16(float lo, float hi) {
    unsigned r; asm("cvt.rn.bf16x2.f32 %0, %1, %2;" : "=r"(r) : "f"(hi), "f"(lo)); return r;
}
__device__ __forceinline__ unsigned f2tf32(float x) {
    unsigned y; asm("cvt.rna.tf32.f32 %0, %1;" : "=r"(y) : "f"(x)); return y;
}
__device__ __forceinline__ uint32_t smem_u32(const void* p) {
    uint32_t a;
    asm("{ .reg .u64 t; cvta.to.shared.u64 t, %1; cvt.u32.u64 %0, t; }" : "=r"(a) : "l"(p));
    return a;
}

#define SWZ64(o) ((o) ^ (((o) >> 3) & 0x30))
#define CP16(dst, src) \
    asm volatile("cp.async.cg.shared.global [%0], [%1], 16;" :: "r"(dst), "l"(src) : "memory")
#define CP_COMMIT() asm volatile("cp.async.commit_group;" ::: "memory")
#define CP_WAIT0()  asm volatile("cp.async.wait_group 0;" ::: "memory")
#define STS128U(addr, r0, r1, r2, r3) \
    asm volatile("st.shared.v4.b32 [%0], {%1,%2,%3,%4};" \
                 :: "r"(addr), "r"(r0), "r"(r1), "r"(r2), "r"(r3) : "memory")
#define LDSM_X4(r0, r1, r2, r3, addr) \
    asm volatile("ldmatrix.sync.aligned.m8n8.x4.shared.b16 {%0,%1,%2,%3}, [%4];" \
                 : "=r"(r0), "=r"(r1), "=r"(r2), "=r"(r3) : "r"(addr))
#define MMA_BF16(d, a0, a1, a2, a3, b0, b1) \
    asm volatile("mma.sync.aligned.m16n8k16.row.col.f32.bf16.bf16.f32 " \
                 "{%0,%1,%2,%3},{%4,%5,%6,%7},{%8,%9},{%0,%1,%2,%3};" \
                 : "+f"((d)[0]), "+f"((d)[1]), "+f"((d)[2]), "+f"((d)[3]) \
                 : "r"(a0), "r"(a1), "r"(a2), "r"(a3), "r"(b0), "r"(b1))

// ===========================================================================
// k_pre: cvt W1 -> bf16 (1MB) + zero g_att
// ===========================================================================
__global__ void k_pre(const float* __restrict__ W1) {
    size_t i = (size_t)blockIdx.x * 256 + threadIdx.x;
    if (i < 131072) {
        float4 v = ((const float4*)W1)[i];
        ((uint2*)g_w1b)[i] = make_uint2(pack_bf16(v.x, v.y), pack_bf16(v.z, v.w));
    } else {
        ((float4*)g_att)[i - 131072] = make_float4(0.f, 0.f, 0.f, 0.f);
    }
}

// ===========================================================================
// k_mlp_att: round-3 skeleton. BM=128, BN=128, BK=32, 256 threads,
//   8 warps of 32x64 tiles, double-buffered SW64 smem.
//   Delta vs round 3: B (W1 bf16) staged via cp.async (issued post-barrier,
//   wait_group 0 pre-barrier) instead of LDG->reg->STS.
//   Fused relu/W2 row-sum epilogue -> atomicAdd g_att.
// ===========================================================================
#define BKG 32
#define NKT (HID/BKG)   // 32

__global__ __launch_bounds__(256, 2)
void k_mlp_att(const float* __restrict__ x,
               const float* __restrict__ b1,
               const float* __restrict__ W2) {
    __shared__ __align__(1024) char smA[2][128 * 64];
    __shared__ __align__(1024) char smB[2][128 * 64];
    __shared__ float b1s[128], w2s[128], s_part[128];

    const int tid  = threadIdx.x;
    const int lane = tid & 31;
    const int warp = tid >> 5;
    const int colBase = blockIdx.x * 128;     // n tile (fastest-varying)
    const int rowBase = blockIdx.y * 128;

    const uint32_t sa0 = smem_u32(&smA[0][0]);
    const uint32_t sa1 = smem_u32(&smA[1][0]);
    const uint32_t sb0 = smem_u32(&smB[0][0]);
    const uint32_t sb1 = smem_u32(&smB[1][0]);

    if (tid < 128) {
        b1s[tid] = b1[colBase + tid];
        w2s[tid] = W2[colBase + tid];
        s_part[tid] = 0.f;
    }

    // 4 m-warps x 2 n-warps, warp tile 32m x 64n
    const int wm = warp & 3, wn = warp >> 2;
    const int mBase = wm * 32, nBase = wn * 64;
    const int g = lane >> 2, t = lane & 3;

    const int aRow = mBase + (lane & 15);
    const int aKb  = (lane >> 4) * 16;
    const int bRow = nBase + (lane & 7) + ((lane >> 4) * 8);
    const int bKb  = ((lane >> 3) & 1) * 16;

    uint32_t aOff[2][2], bOff[4][2];
    #pragma unroll
    for (int mi = 0; mi < 2; mi++)
        #pragma unroll
        for (int ks = 0; ks < 2; ks++)
            aOff[mi][ks] = SWZ64((uint32_t)((aRow + mi * 16) * 64 + ks * 32 + aKb));
    #pragma unroll
    for (int nj = 0; nj < 4; nj++)
        #pragma unroll
        for (int ks = 0; ks < 2; ks++)
            bOff[nj][ks] = SWZ64((uint32_t)((bRow + nj * 16) * 64 + ks * 32 + bKb));

    float acc[2][8][4];
    #pragma unroll
    for (int mi = 0; mi < 2; mi++)
        #pragma unroll
        for (int ni = 0; ni < 8; ni++)
            #pragma unroll
            for (int q = 0; q < 4; q++) acc[mi][ni][q] = 0.f;

    // A staging (fp32 -> bf16 via regs): rows arow0, arow0+64; 8 floats each
    const int arow0 = tid >> 2;
    const int ac8   = (tid & 3) * 8;
    auto ldA = [&](int kc, float4* st) {
        const int k0 = kc * BKG;
        #pragma unroll
        for (int it = 0; it < 2; ++it) {
            int row = arow0 + it * 64;
            const float4* p = (const float4*)(x + (size_t)(rowBase + row) * HID + k0 + ac8);
            st[it * 2]     = p[0];
            st[it * 2 + 1] = p[1];
        }
    };
    auto stA = [&](uint32_t base, const float4* st) {
        #pragma unroll
        for (int it = 0; it < 2; ++it) {
            int row = arow0 + it * 64;
            float4 v0 = st[it * 2], v1 = st[it * 2 + 1];
            uint32_t off = (uint32_t)(row * 64 + ac8 * 2);
            STS128U(base + SWZ64(off),
                    pack_bf16(v0.x, v0.y), pack_bf16(v0.z, v0.w),
                    pack_bf16(v1.x, v1.y), pack_bf16(v1.z, v1.w));
        }
    };

    // B staging via cp.async: row = tid>>1, two 16B chunks at (tid&1)*2
    const int brow = tid >> 1;
    const int bc0  = (tid & 1) * 2;
    const __nv_bfloat16* bSrc = g_w1b + (size_t)(colBase + brow) * HID + bc0 * 8;
    const uint32_t bD0 = SWZ64((uint32_t)(brow * 64 + bc0 * 16));
    const uint32_t bD1 = SWZ64((uint32_t)(brow * 64 + bc0 * 16 + 16));

    // prologue: fill stage 0
    {
        CP16(sb0 + bD0, bSrc);
        CP16(sb0 + bD1, bSrc + 8);
        CP_COMMIT();
        float4 fa[4];
        ldA(0, fa);
        stA(sa0, fa);
        CP_WAIT0();
    }
    __syncthreads();

    float4 fa[4];
    for (int kt = 0; kt < NKT; ++kt) {
        const uint32_t aBase = (kt & 1) ? sa1 : sa0;
        const uint32_t bBase = (kt & 1) ? sb1 : sb0;
        const uint32_t aN    = (kt & 1) ? sa0 : sa1;
        const uint32_t bN    = (kt & 1) ? sb0 : sb1;

        if (kt < NKT - 1) {
            // B next stage: async copy into the buffer not read this iteration
            CP16(bN + bD0, bSrc + (kt + 1) * 32);
            CP16(bN + bD1, bSrc + (kt + 1) * 32 + 8);
            CP_COMMIT();
            ldA(kt + 1, fa);
        }

        #pragma unroll
        for (int ks = 0; ks < 2; ++ks) {
            uint32_t a[2][4];
            #pragma unroll
            for (int mi = 0; mi < 2; mi++)
                LDSM_X4(a[mi][0], a[mi][1], a[mi][2], a[mi][3], aBase + aOff[mi][ks]);
            #pragma unroll
            for (int nj = 0; nj < 4; nj++) {
                uint32_t b0, b1r, b2, b3;
                LDSM_X4(b0, b1r, b2, b3, bBase + bOff[nj][ks]);
                #pragma unroll
                for (int mi = 0; mi < 2; mi++) {
                    MMA_BF16(acc[mi][nj * 2],     a[mi][0], a[mi][1], a[mi][2], a[mi][3], b0, b1r);
                    MMA_BF16(acc[mi][nj * 2 + 1], a[mi][0], a[mi][1], a[mi][2], a[mi][3], b2, b3);
                }
            }
        }
        if (kt < NKT - 1) {
            stA(aN, fa);
            CP_WAIT0();
        }
        __syncthreads();
    }

    // epilogue: relu(acc + b1) * W2, reduce over this CTA's 128 cols
    float rs00 = 0.f, rs01 = 0.f, rs10 = 0.f, rs11 = 0.f;
    #pragma unroll
    for (int mi = 0; mi < 2; mi++) {
        float s0 = 0.f, s1 = 0.f;
        #pragma unroll
        for (int ni = 0; ni < 8; ni++) {
            int c = nBase + ni * 8 + t * 2;
            s0 += fmaxf(acc[mi][ni][0] + b1s[c],     0.f) * w2s[c]
                + fmaxf(acc[mi][ni][1] + b1s[c + 1], 0.f) * w2s[c + 1];
            s1 += fmaxf(acc[mi][ni][2] + b1s[c],     0.f) * w2s[c]
                + fmaxf(acc[mi][ni][3] + b1s[c + 1], 0.f) * w2s[c + 1];
        }
        if (mi == 0) { rs00 = s0; rs01 = s1; } else { rs10 = s0; rs11 = s1; }
    }
    #pragma unroll
    for (int off = 1; off < 4; off <<= 1) {
        rs00 += __shfl_xor_sync(0xffffffff, rs00, off);
        rs01 += __shfl_xor_sync(0xffffffff, rs01, off);
        rs10 += __shfl_xor_sync(0xffffffff, rs10, off);
        rs11 += __shfl_xor_sync(0xffffffff, rs11, off);
    }
    if (t == 0) {
        atomicAdd(&s_part[mBase + g],      rs00);
        atomicAdd(&s_part[mBase + 8 + g],  rs01);
        atomicAdd(&s_part[mBase + 16 + g], rs10);
        atomicAdd(&s_part[mBase + 24 + g], rs11);
    }
    __syncthreads();
    if (tid < 128) atomicAdd(&g_att[rowBase + tid], s_part[tid]);
}

// ===========================================================================
// k_stats4: per-batch softmax/moments/r/w, then h-sliced context stream.
// ===========================================================================
__global__ __launch_bounds__(256)
void k_stats4(const float* __restrict__ x,
              const unsigned char* __restrict__ mask,
              const float* __restrict__ G,
              const float* __restrict__ mub) {
    __shared__ float smax[8], ssum[8][6];
    __shared__ float r_s[NB], w_s[SEQ];
    __shared__ float4 red[256];

    const int b = blockIdx.y, slice = blockIdx.x;
    const int tid = threadIdx.x, lane = tid & 31, warp = tid >> 5;

    float logit = -3.0e38f;
    if (tid < SEQ) {
        logit = g_att[b * SEQ + tid];
        if (mask[b * SEQ + tid]) logit = -1.0e9f;
    }
    float v = logit;
    #pragma unroll
    for (int off = 16; off > 0; off >>= 1) v = fmaxf(v, __shfl_xor_sync(0xffffffff, v, off));
    if (lane == 0) smax[warp] = v;
    __syncthreads();
    float mx = smax[0];
    #pragma unroll
    for (int w = 1; w < 8; w++) mx = fmaxf(mx, smax[w]);

    float e = (tid < SEQ) ? expf(logit - mx) : 0.f;
    float px = 0.f, py = 0.f;
    if (tid < SEQ) { px = (float)(tid / 14) * (1.f / 13.f); py = (float)(tid % 14) * (1.f / 13.f); }
    float s6[6] = { e, e * px, e * py, e * px * px, e * px * py, e * py * py };
    #pragma unroll
    for (int q = 0; q < 6; q++) {
        float sv = s6[q];
        #pragma unroll
        for (int off = 16; off > 0; off >>= 1) sv += __shfl_xor_sync(0xffffffff, sv, off);
        if (lane == 0) ssum[warp][q] = sv;
    }
    __syncthreads();
    float sums[6];
    #pragma unroll
    for (int q = 0; q < 6; q++) {
        float sv = 0.f;
        #pragma unroll
        for (int w = 0; w < 8; w++) sv += ssum[w][q];
        sums[q] = sv;
    }

    const float S   = sums[0];
    const float Mux = sums[1] / S, Muy = sums[2] / S;
    float S00 = sums[3] / S - Mux * Mux + 1e-6f;
    float S01 = sums[4] / S - Mux * Muy;
    float S11 = sums[5] / S - Muy * Muy + 1e-6f;
    float det = S00 * S11 - S01 * S01;
    float I00 = S11 / det, I01 = -S01 / det, I11 = S00 / det;
    float t0 = I00 * Mux + I01 * Muy;
    float t1 = I01 * Mux + I11 * Muy;
    float ds = I00 * I11 - I01 * I01;
    float R00 = I11 / ds, R01 = -I01 / ds, R11 = I00 / ds;
    float m0 = R00 * t0 + R01 * t1;
    float m1 = R01 * t0 + R11 * t1;
    float A00 = R00 + 1e-3f, A01 = R01, A11 = R11 + 1e-3f;
    float detA = A00 * A11 - A01 * A01;
    float Ai00 = A11 / detA, Ai01 = -A01 / detA, Ai11 = A00 / detA;
    float coef = 1.f / (6.2831853071795864769f * sqrtf(detA));

    if (tid < NB) {
        float d0 = m0 - mub[2 * tid];
        float d1 = m1 - mub[2 * tid + 1];
        float quad = d0 * (Ai00 * d0 + Ai01 * d1) + d1 * (Ai01 * d0 + Ai11 * d1);
        r_s[tid] = expf(-0.5f * quad) * coef;
    }
    __syncthreads();
    if (tid < SEQ) {
        float wv = 0.f;
        #pragma unroll 4
        for (int k = 0; k < NB; k++) wv += G[tid * NB + k] * r_s[k];
        w_s[tid] = wv;
    }
    __syncthreads();

    const int h4 = tid & 63, nn = tid >> 6;
    const float4* xb = (const float4*)(x + (size_t)b * SEQ * HID) + slice * 64 + h4;
    float ax = 0.f, ay = 0.f, az = 0.f, aw = 0.f;
    #pragma unroll 7
    for (int n = nn; n < SEQ; n += 4) {
        float4 vv = xb[n * 256];
        float wv = w_s[n];
        ax += wv * vv.x; ay += wv * vv.y; az += wv * vv.z; aw += wv * vv.w;
    }
    red[tid] = make_float4(ax, ay, az, aw);
    __syncthreads();
    if (tid < 64) {
        float4 a0 = red[tid], a1 = red[tid + 64], a2 = red[tid + 128], a3 = red[tid + 192];
        float4 o;
        o.x = a0.x + a1.x + a2.x + a3.x;
        o.y = a0.y + a1.y + a2.y + a3.y;
        o.z = a0.z + a1.z + a2.z + a3.z;
        o.w = a0.w + a1.w + a2.w + a3.w;
        ((float4*)(g_ctx + (size_t)b * HID + slice * 256))[tid] = o;
    }
}

// ===========================================================================
// k_out2: out = ctx(512x1024) @ Wm^T + bm  (tf32 mma.sync, BM=64 BN=128)
//   (measured best config: 45us)
// ===========================================================================
#define BM2 64
#define BN2 128
#define XS2 20

__global__ __launch_bounds__(256, 2)
void k_out2(const float* __restrict__ Wm, const float* __restrict__ bm,
            float* __restrict__ out) {
    __shared__ unsigned sa[2][BM2][XS2];
    __shared__ unsigned sbm[2][BN2][XS2];

    const int tid = threadIdx.x;
    const int mB = blockIdx.x * BM2, nB = blockIdx.y * BN2;
    const int lr = tid >> 2, lc = (tid & 3) * 4;
    const int warp = tid >> 5, lane = tid & 31;
    const int wm = warp & 1, wn = warp >> 1;
    const int mBase = wm * 32, nBase = wn * 32;
    const int g = lane >> 2, t = lane & 3;

    float acc[2][4][4];
    #pragma unroll
    for (int mi = 0; mi < 2; mi++)
        #pragma unroll
        for (int ni = 0; ni < 4; ni++)
            #pragma unroll
            for (int q = 0; q < 4; q++) acc[mi][ni][q] = 0.f;

    float4 pa, pb0, pb1;
    pa  = *(const float4*)&g_ctx[(size_t)(mB + lr) * HID + lc];
    pb0 = *(const float4*)&Wm  [(size_t)(nB + lr) * HID + lc];
    pb1 = *(const float4*)&Wm  [(size_t)(nB + lr + 64) * HID + lc];
    sa [0][lr][lc+0] = f2tf32(pa.x);  sa [0][lr][lc+1] = f2tf32(pa.y);
    sa [0][lr][lc+2] = f2tf32(pa.z);  sa [0][lr][lc+3] = f2tf32(pa.w);
    sbm[0][lr][lc+0] = f2tf32(pb0.x); sbm[0][lr][lc+1] = f2tf32(pb0.y);
    sbm[0][lr][lc+2] = f2tf32(pb0.z); sbm[0][lr][lc+3] = f2tf32(pb0.w);
    sbm[0][lr+64][lc+0] = f2tf32(pb1.x); sbm[0][lr+64][lc+1] = f2tf32(pb1.y);
    sbm[0][lr+64][lc+2] = f2tf32(pb1.z); sbm[0][lr+64][lc+3] = f2tf32(pb1.w);
    __syncthreads();

    const int NT = HID / 16;
    for (int kt = 0; kt < NT; ++kt) {
        const int buf = kt & 1;
        if (kt < NT - 1) {
            int k0 = (kt + 1) * 16;
            pa  = *(const float4*)&g_ctx[(size_t)(mB + lr) * HID + k0 + lc];
            pb0 = *(const float4*)&Wm  [(size_t)(nB + lr) * HID + k0 + lc];
            pb1 = *(const float4*)&Wm  [(size_t)(nB + lr + 64) * HID + k0 + lc];
        }
        #pragma unroll
        for (int ks = 0; ks < 2; ++ks) {
            const int k0s = ks * 8;
            unsigned a[2][4], bf[4][2];
            #pragma unroll
            for (int mi = 0; mi < 2; mi++) {
                int r0 = mBase + mi * 16 + g;
                a[mi][0] = sa[buf][r0    ][k0s + t];
                a[mi][1] = sa[buf][r0 + 8][k0s + t];
                a[mi][2] = sa[buf][r0    ][k0s + t + 4];
                a[mi][3] = sa[buf][r0 + 8][k0s + t + 4];
            }
            #pragma unroll
            for (int ni = 0; ni < 4; ni++) {
                int c0 = nBase + ni * 8 + g;
                bf[ni][0] = sbm[buf][c0][k0s + t];
                bf[ni][1] = sbm[buf][c0][k0s + t + 4];
            }
            #pragma unroll
            for (int mi = 0; mi < 2; mi++)
                #pragma unroll
                for (int ni = 0; ni < 4; ni++)
                    asm volatile(
                        "mma.sync.aligned.m16n8k8.row.col.f32.tf32.tf32.f32 "
                        "{%0,%1,%2,%3},{%4,%5,%6,%7},{%8,%9},{%0,%1,%2,%3};"
                        : "+f"(acc[mi][ni][0]), "+f"(acc[mi][ni][1]),
                          "+f"(acc[mi][ni][2]), "+f"(acc[mi][ni][3])
                        : "r"(a[mi][0]), "r"(a[mi][1]), "r"(a[mi][2]), "r"(a[mi][3]),
                          "r"(bf[ni][0]), "r"(bf[ni][1]));
        }
        if (kt < NT - 1) {
            int nb = buf ^ 1;
            sa [nb][lr][lc+0] = f2tf32(pa.x);  sa [nb][lr][lc+1] = f2tf32(pa.y);
            sa [nb][lr][lc+2] = f2tf32(pa.z);  sa [nb][lr][lc+3] = f2tf32(pa.w);
            sbm[nb][lr][lc+0] = f2tf32(pb0.x); sbm[nb][lr][lc+1] = f2tf32(pb0.y);
            sbm[nb][lr][lc+2] = f2tf32(pb0.z); sbm[nb][lr][lc+3] = f2tf32(pb0.w);
            sbm[nb][lr+64][lc+0] = f2tf32(pb1.x); sbm[nb][lr+64][lc+1] = f2tf32(pb1.y);
            sbm[nb][lr+64][lc+2] = f2tf32(pb1.z); sbm[nb][lr+64][lc+3] = f2tf32(pb1.w);
        }
        __syncthreads();
    }

    #pragma unroll
    for (int mi = 0; mi < 2; mi++)
        #pragma unroll
        for (int ni = 0; ni < 4; ni++) {
            int r0 = mB + mBase + mi * 16 + g;
            int c0 = nB + nBase + ni * 8 + t * 2;
            float bm0 = bm[c0], bm1 = bm[c0 + 1];
            out[(size_t)r0 * FOUT + c0]           = acc[mi][ni][0] + bm0;
            out[(size_t)r0 * FOUT + c0 + 1]       = acc[mi][ni][1] + bm1;
            out[(size_t)(r0 + 8) * FOUT + c0]     = acc[mi][ni][2] + bm0;
            out[(size_t)(r0 + 8) * FOUT + c0 + 1] = acc[mi][ni][3] + bm1;
        }
}

// ---------------------------------------------------------------------------
extern "C" void kernel_launch(void* const* d_in, const int* in_sizes, int n_in,
                              void* d_out, int out_size) {
    const float*         x   = (const float*)d_in[0];
    const unsigned char* xm  = (const unsigned char*)d_in[1];
    const float*         W1  = (const float*)d_in[2];
    const float*         b1  = (const float*)d_in[3];
    const float*         W2  = (const float*)d_in[4];
    // d_in[5] = b2: softmax-invariant
    const float*         Wm  = (const float*)d_in[6];
    const float*         bm  = (const float*)d_in[7];
    const float*         G   = (const float*)d_in[8];
    const float*         mub = (const float*)d_in[9];
    float* out = (float*)d_out;

    k_pre<<<610, 256>>>(W1);
    k_mlp_att<<<dim3(4, ROWS / 128), 256>>>(x, b1, W2);
    k_stats4<<<dim3(4, BATCH), 256>>>(x, xm, G, mub);
    k_out2<<<dim3(BATCH / BM2, FOUT / BN2), 256>>>(Wm, bm, out);
}

// round 9
// speedup vs baseline: 1.4542x; 1.1080x over previous
#include <cuda_runtime.h>
#include <cuda_bf16.h>
#include <math.h>
#include <stdint.h>

#define BATCH 512
#define SEQ   196
#define HID   1024
#define MID   512
#define FOUT  2048
#define NB    100
#define ROWS  (BATCH*SEQ)      // 100352

__device__ __align__(16) float g_att[ROWS];
__device__ __align__(16) float g_ctx[BATCH*HID];
__device__ __align__(16) __nv_bfloat16 g_w1b[MID*HID];

__device__ __forceinline__ unsigned pack_bf16(float lo, float hi) {
    unsigned r; asm("cvt.rn.bf16x2.f32 %0, %1, %2;" : "=r"(r) : "f"(hi), "f"(lo)); return r;
}
__device__ __forceinline__ unsigned f2tf32(float x) {
    unsigned y; asm("cvt.rna.tf32.f32 %0, %1;" : "=r"(y) : "f"(x)); return y;
}
__device__ __forceinline__ uint32_t smem_u32(const void* p) {
    uint32_t a;
    asm("{ .reg .u64 t; cvta.to.shared.u64 t, %1; cvt.u32.u64 %0, t; }" : "=r"(a) : "l"(p));
    return a;
}

// 64B-row swizzle (SW64): XOR bits [5:4] with bits [8:7]
#define SWZ64(o) ((o) ^ (((o) >> 3) & 0x30))

#define STS128U(addr, r0, r1, r2, r3) \
    asm volatile("st.shared.v4.b32 [%0], {%1,%2,%3,%4};" \
                 :: "r"(addr), "r"(r0), "r"(r1), "r"(r2), "r"(r3) : "memory")
#define LDSM_X4(r0, r1, r2, r3, addr) \
    asm volatile("ldmatrix.sync.aligned.m8n8.x4.shared.b16 {%0,%1,%2,%3}, [%4];" \
                 : "=r"(r0), "=r"(r1), "=r"(r2), "=r"(r3) : "r"(addr))
#define MMA_BF16(d, a0, a1, a2, a3, b0, b1) \
    asm volatile("mma.sync.aligned.m16n8k16.row.col.f32.bf16.bf16.f32 " \
                 "{%0,%1,%2,%3},{%4,%5,%6,%7},{%8,%9},{%0,%1,%2,%3};" \
                 : "+f"((d)[0]), "+f"((d)[1]), "+f"((d)[2]), "+f"((d)[3]) \
                 : "r"(a0), "r"(a1), "r"(a2), "r"(a3), "r"(b0), "r"(b1))

// ===========================================================================
// k_pre: cvt W1 -> bf16 (1MB) + zero g_att
// ===========================================================================
__global__ void k_pre(const float* __restrict__ W1) {
    size_t i = (size_t)blockIdx.x * 256 + threadIdx.x;
    if (i < 131072) {
        float4 v = ((const float4*)W1)[i];
        ((uint2*)g_w1b)[i] = make_uint2(pack_bf16(v.x, v.y), pack_bf16(v.z, v.w));
    } else {
        ((float4*)g_att)[i - 131072] = make_float4(0.f, 0.f, 0.f, 0.f);
    }
}

// ===========================================================================
// k_mlp_att: EXACT round-3 GEMM (measured best: ~360us).
//   BM=128, BN=128, BK=32, 256 threads, 8 warps of 32x64 tiles,
//   double-buffered SW64 smem, register-staged LDG->cvt->STS for A and B.
//   Fused relu/W2 row-sum epilogue -> atomicAdd g_att.
// ===========================================================================
#define BKG 32
#define NKT (HID/BKG)   // 32

__global__ __launch_bounds__(256, 2)
void k_mlp_att(const float* __restrict__ x,
               const float* __restrict__ b1,
               const float* __restrict__ W2) {
    __shared__ __align__(1024) char smA[2][128 * 64];
    __shared__ __align__(1024) char smB[2][128 * 64];
    __shared__ float b1s[128], w2s[128], s_part[128];

    const int tid  = threadIdx.x;
    const int lane = tid & 31;
    const int warp = tid >> 5;
    const int colBase = blockIdx.x * 128;     // n tile (fastest-varying)
    const int rowBase = blockIdx.y * 128;     // row tile

    const uint32_t sa0 = smem_u32(&smA[0][0]);
    const uint32_t sa1 = smem_u32(&smA[1][0]);
    const uint32_t sb0 = smem_u32(&smB[0][0]);
    const uint32_t sb1 = smem_u32(&smB[1][0]);

    if (tid < 128) {
        b1s[tid] = b1[colBase + tid];
        w2s[tid] = W2[colBase + tid];
        s_part[tid] = 0.f;
    }

    // warp tiling: 4 m-warps x 2 n-warps, warp tile 32m x 64n
    const int wm = warp & 3, wn = warp >> 2;
    const int mBase = wm * 32, nBase = wn * 64;
    const int g = lane >> 2, t = lane & 3;

    const int aRow = mBase + (lane & 15);
    const int aKb  = (lane >> 4) * 16;
    const int bRow = nBase + (lane & 7) + ((lane >> 4) * 8);
    const int bKb  = ((lane >> 3) & 1) * 16;

    uint32_t aOff[2][2], bOff[4][2];
    #pragma unroll
    for (int mi = 0; mi < 2; mi++)
        #pragma unroll
        for (int ks = 0; ks < 2; ks++)
            aOff[mi][ks] = SWZ64((uint32_t)((aRow + mi * 16) * 64 + ks * 32 + aKb));
    #pragma unroll
    for (int nj = 0; nj < 4; nj++)
        #pragma unroll
        for (int ks = 0; ks < 2; ks++)
            bOff[nj][ks] = SWZ64((uint32_t)((bRow + nj * 16) * 64 + ks * 32 + bKb));

    float acc[2][8][4];
    #pragma unroll
    for (int mi = 0; mi < 2; mi++)
        #pragma unroll
        for (int ni = 0; ni < 8; ni++)
            #pragma unroll
            for (int q = 0; q < 4; q++) acc[mi][ni][q] = 0.f;

    // ---- stage loaders ----
    const int arow0 = tid >> 2;            // task row for it=0
    const int ac8   = (tid & 3) * 8;       // float col within k-chunk
    auto ldA = [&](int kc, float4* st) {
        const int k0 = kc * BKG;
        #pragma unroll
        for (int it = 0; it < 2; ++it) {
            int row = arow0 + it * 64;
            const float4* p = (const float4*)(x + (size_t)(rowBase + row) * HID + k0 + ac8);
            st[it * 2]     = p[0];
            st[it * 2 + 1] = p[1];
        }
    };
    auto stA = [&](uint32_t base, const float4* st) {
        #pragma unroll
        for (int it = 0; it < 2; ++it) {
            int row = arow0 + it * 64;
            float4 v0 = st[it * 2], v1 = st[it * 2 + 1];
            unsigned u0 = pack_bf16(v0.x, v0.y), u1 = pack_bf16(v0.z, v0.w);
            unsigned u2 = pack_bf16(v1.x, v1.y), u3 = pack_bf16(v1.z, v1.w);
            uint32_t off = (uint32_t)(row * 64 + ac8 * 2);
            STS128U(base + SWZ64(off), u0, u1, u2, u3);
        }
    };
    auto ldB = [&](int kc, uint4* st) {
        const int k0 = kc * BKG;
        #pragma unroll
        for (int it = 0; it < 2; ++it) {
            int task = tid + it * 256;
            int row = task >> 2;
            int e8  = (task & 3) * 8;
            st[it] = *(const uint4*)(g_w1b + (size_t)(colBase + row) * HID + k0 + e8);
        }
    };
    auto stB = [&](uint32_t base, const uint4* st) {
        #pragma unroll
        for (int it = 0; it < 2; ++it) {
            int task = tid + it * 256;
            int row = task >> 2;
            int c16 = (task & 3) * 16;
            uint32_t off = (uint32_t)(row * 64 + c16);
            STS128U(base + SWZ64(off), st[it].x, st[it].y, st[it].z, st[it].w);
        }
    };

    // prologue: fill stage 0
    {
        float4 fa[4]; uint4 fb[2];
        ldA(0, fa); ldB(0, fb);
        stA(sa0, fa); stB(sb0, fb);
    }
    __syncthreads();

    float4 fa[4]; uint4 fb[2];
    for (int kt = 0; kt < NKT; ++kt) {
        const uint32_t aBase = (kt & 1) ? sa1 : sa0;
        const uint32_t bBase = (kt & 1) ? sb1 : sb0;
        if (kt < NKT - 1) { ldA(kt + 1, fa); ldB(kt + 1, fb); }

        #pragma unroll
        for (int ks = 0; ks < 2; ++ks) {
            uint32_t a[2][4];
            #pragma unroll
            for (int mi = 0; mi < 2; mi++)
                LDSM_X4(a[mi][0], a[mi][1], a[mi][2], a[mi][3], aBase + aOff[mi][ks]);
            #pragma unroll
            for (int nj = 0; nj < 4; nj++) {
                uint32_t b0, b1r, b2, b3;
                LDSM_X4(b0, b1r, b2, b3, bBase + bOff[nj][ks]);
                #pragma unroll
                for (int mi = 0; mi < 2; mi++) {
                    MMA_BF16(acc[mi][nj * 2],     a[mi][0], a[mi][1], a[mi][2], a[mi][3], b0, b1r);
                    MMA_BF16(acc[mi][nj * 2 + 1], a[mi][0], a[mi][1], a[mi][2], a[mi][3], b2, b3);
                }
            }
        }
        if (kt < NKT - 1) {
            const uint32_t aN = (kt & 1) ? sa0 : sa1;
            const uint32_t bN = (kt & 1) ? sb0 : sb1;
            stA(aN, fa); stB(bN, fb);
        }
        __syncthreads();
    }

    // Epilogue: relu(acc + b1) * W2, reduce over this CTA's 128 cols.
    float rs00 = 0.f, rs01 = 0.f, rs10 = 0.f, rs11 = 0.f;
    #pragma unroll
    for (int mi = 0; mi < 2; mi++) {
        float s0 = 0.f, s1 = 0.f;
        #pragma unroll
        for (int ni = 0; ni < 8; ni++) {
            int c = nBase + ni * 8 + t * 2;
            s0 += fmaxf(acc[mi][ni][0] + b1s[c],     0.f) * w2s[c]
                + fmaxf(acc[mi][ni][1] + b1s[c + 1], 0.f) * w2s[c + 1];
            s1 += fmaxf(acc[mi][ni][2] + b1s[c],     0.f) * w2s[c]
                + fmaxf(acc[mi][ni][3] + b1s[c + 1], 0.f) * w2s[c + 1];
        }
        if (mi == 0) { rs00 = s0; rs01 = s1; } else { rs10 = s0; rs11 = s1; }
    }
    #pragma unroll
    for (int off = 1; off < 4; off <<= 1) {
        rs00 += __shfl_xor_sync(0xffffffff, rs00, off);
        rs01 += __shfl_xor_sync(0xffffffff, rs01, off);
        rs10 += __shfl_xor_sync(0xffffffff, rs10, off);
        rs11 += __shfl_xor_sync(0xffffffff, rs11, off);
    }
    if (t == 0) {
        atomicAdd(&s_part[mBase + g],      rs00);
        atomicAdd(&s_part[mBase + 8 + g],  rs01);
        atomicAdd(&s_part[mBase + 16 + g], rs10);
        atomicAdd(&s_part[mBase + 24 + g], rs11);
    }
    __syncthreads();
    if (tid < 128) atomicAdd(&g_att[rowBase + tid], s_part[tid]);
}

// ===========================================================================
// k_stats4: per-batch softmax/moments/r/w, then h-sliced context stream.
// ===========================================================================
__global__ __launch_bounds__(256)
void k_stats4(const float* __restrict__ x,
              const unsigned char* __restrict__ mask,
              const float* __restrict__ G,
              const float* __restrict__ mub) {
    __shared__ float smax[8], ssum[8][6];
    __shared__ float r_s[NB], w_s[SEQ];
    __shared__ float4 red[256];

    const int b = blockIdx.y, slice = blockIdx.x;
    const int tid = threadIdx.x, lane = tid & 31, warp = tid >> 5;

    float logit = -3.0e38f;
    if (tid < SEQ) {
        logit = g_att[b * SEQ + tid];
        if (mask[b * SEQ + tid]) logit = -1.0e9f;
    }
    float v = logit;
    #pragma unroll
    for (int off = 16; off > 0; off >>= 1) v = fmaxf(v, __shfl_xor_sync(0xffffffff, v, off));
    if (lane == 0) smax[warp] = v;
    __syncthreads();
    float mx = smax[0];
    #pragma unroll
    for (int w = 1; w < 8; w++) mx = fmaxf(mx, smax[w]);

    float e = (tid < SEQ) ? expf(logit - mx) : 0.f;
    float px = 0.f, py = 0.f;
    if (tid < SEQ) { px = (float)(tid / 14) * (1.f / 13.f); py = (float)(tid % 14) * (1.f / 13.f); }
    float s6[6] = { e, e * px, e * py, e * px * px, e * px * py, e * py * py };
    #pragma unroll
    for (int q = 0; q < 6; q++) {
        float sv = s6[q];
        #pragma unroll
        for (int off = 16; off > 0; off >>= 1) sv += __shfl_xor_sync(0xffffffff, sv, off);
        if (lane == 0) ssum[warp][q] = sv;
    }
    __syncthreads();
    float sums[6];
    #pragma unroll
    for (int q = 0; q < 6; q++) {
        float sv = 0.f;
        #pragma unroll
        for (int w = 0; w < 8; w++) sv += ssum[w][q];
        sums[q] = sv;
    }

    const float S   = sums[0];
    const float Mux = sums[1] / S, Muy = sums[2] / S;
    float S00 = sums[3] / S - Mux * Mux + 1e-6f;
    float S01 = sums[4] / S - Mux * Muy;
    float S11 = sums[5] / S - Muy * Muy + 1e-6f;
    float det = S00 * S11 - S01 * S01;
    float I00 = S11 / det, I01 = -S01 / det, I11 = S00 / det;
    float t0 = I00 * Mux + I01 * Muy;
    float t1 = I01 * Mux + I11 * Muy;
    float ds = I00 * I11 - I01 * I01;
    float R00 = I11 / ds, R01 = -I01 / ds, R11 = I00 / ds;
    float m0 = R00 * t0 + R01 * t1;
    float m1 = R01 * t0 + R11 * t1;
    float A00 = R00 + 1e-3f, A01 = R01, A11 = R11 + 1e-3f;
    float detA = A00 * A11 - A01 * A01;
    float Ai00 = A11 / detA, Ai01 = -A01 / detA, Ai11 = A00 / detA;
    float coef = 1.f / (6.2831853071795864769f * sqrtf(detA));

    if (tid < NB) {
        float d0 = m0 - mub[2 * tid];
        float d1 = m1 - mub[2 * tid + 1];
        float quad = d0 * (Ai00 * d0 + Ai01 * d1) + d1 * (Ai01 * d0 + Ai11 * d1);
        r_s[tid] = expf(-0.5f * quad) * coef;
    }
    __syncthreads();
    if (tid < SEQ) {
        float wv = 0.f;
        #pragma unroll 4
        for (int k = 0; k < NB; k++) wv += G[tid * NB + k] * r_s[k];
        w_s[tid] = wv;
    }
    __syncthreads();

    const int h4 = tid & 63, nn = tid >> 6;
    const float4* xb = (const float4*)(x + (size_t)b * SEQ * HID) + slice * 64 + h4;
    float ax = 0.f, ay = 0.f, az = 0.f, aw = 0.f;
    #pragma unroll 7
    for (int n = nn; n < SEQ; n += 4) {
        float4 vv = xb[n * 256];
        float wv = w_s[n];
        ax += wv * vv.x; ay += wv * vv.y; az += wv * vv.z; aw += wv * vv.w;
    }
    red[tid] = make_float4(ax, ay, az, aw);
    __syncthreads();
    if (tid < 64) {
        float4 a0 = red[tid], a1 = red[tid + 64], a2 = red[tid + 128], a3 = red[tid + 192];
        float4 o;
        o.x = a0.x + a1.x + a2.x + a3.x;
        o.y = a0.y + a1.y + a2.y + a3.y;
        o.z = a0.z + a1.z + a2.z + a3.z;
        o.w = a0.w + a1.w + a2.w + a3.w;
        ((float4*)(g_ctx + (size_t)b * HID + slice * 256))[tid] = o;
    }
}

// ===========================================================================
// k_out2: out = ctx(512x1024) @ Wm^T + bm  (tf32 mma.sync, BM=64 BN=128)
// ===========================================================================
#define BM2 64
#define BN2 128
#define XS2 20

__global__ __launch_bounds__(256, 2)
void k_out2(const float* __restrict__ Wm, const float* __restrict__ bm,
            float* __restrict__ out) {
    __shared__ unsigned sa[2][BM2][XS2];
    __shared__ unsigned sbm[2][BN2][XS2];

    const int tid = threadIdx.x;
    const int mB = blockIdx.x * BM2, nB = blockIdx.y * BN2;
    const int lr = tid >> 2, lc = (tid & 3) * 4;
    const int warp = tid >> 5, lane = tid & 31;
    const int wm = warp & 1, wn = warp >> 1;
    const int mBase = wm * 32, nBase = wn * 32;
    const int g = lane >> 2, t = lane & 3;

    float acc[2][4][4];
    #pragma unroll
    for (int mi = 0; mi < 2; mi++)
        #pragma unroll
        for (int ni = 0; ni < 4; ni++)
            #pragma unroll
            for (int q = 0; q < 4; q++) acc[mi][ni][q] = 0.f;

    float4 pa, pb0, pb1;
    pa  = *(const float4*)&g_ctx[(size_t)(mB + lr) * HID + lc];
    pb0 = *(const float4*)&Wm  [(size_t)(nB + lr) * HID + lc];
    pb1 = *(const float4*)&Wm  [(size_t)(nB + lr + 64) * HID + lc];
    sa [0][lr][lc+0] = f2tf32(pa.x);  sa [0][lr][lc+1] = f2tf32(pa.y);
    sa [0][lr][lc+2] = f2tf32(pa.z);  sa [0][lr][lc+3] = f2tf32(pa.w);
    sbm[0][lr][lc+0] = f2tf32(pb0.x); sbm[0][lr][lc+1] = f2tf32(pb0.y);
    sbm[0][lr][lc+2] = f2tf32(pb0.z); sbm[0][lr][lc+3] = f2tf32(pb0.w);
    sbm[0][lr+64][lc+0] = f2tf32(pb1.x); sbm[0][lr+64][lc+1] = f2tf32(pb1.y);
    sbm[0][lr+64][lc+2] = f2tf32(pb1.z); sbm[0][lr+64][lc+3] = f2tf32(pb1.w);
    __syncthreads();

    const int NT = HID / 16;
    for (int kt = 0; kt < NT; ++kt) {
        const int buf = kt & 1;
        if (kt < NT - 1) {
            int k0 = (kt + 1) * 16;
            pa  = *(const float4*)&g_ctx[(size_t)(mB + lr) * HID + k0 + lc];
            pb0 = *(const float4*)&Wm  [(size_t)(nB + lr) * HID + k0 + lc];
            pb1 = *(const float4*)&Wm  [(size_t)(nB + lr + 64) * HID + k0 + lc];
        }
        #pragma unroll
        for (int ks = 0; ks < 2; ++ks) {
            const int k0s = ks * 8;
            unsigned a[2][4], bf[4][2];
            #pragma unroll
            for (int mi = 0; mi < 2; mi++) {
                int r0 = mBase + mi * 16 + g;
                a[mi][0] = sa[buf][r0    ][k0s + t];
                a[mi][1] = sa[buf][r0 + 8][k0s + t];
                a[mi][2] = sa[buf][r0    ][k0s + t + 4];
                a[mi][3] = sa[buf][r0 + 8][k0s + t + 4];
            }
            #pragma unroll
            for (int ni = 0; ni < 4; ni++) {
                int c0 = nBase + ni * 8 + g;
                bf[ni][0] = sbm[buf][c0][k0s + t];
                bf[ni][1] = sbm[buf][c0][k0s + t + 4];
            }
            #pragma unroll
            for (int mi = 0; mi < 2; mi++)
                #pragma unroll
                for (int ni = 0; ni < 4; ni++)
                    asm volatile(
                        "mma.sync.aligned.m16n8k8.row.col.f32.tf32.tf32.f32 "
                        "{%0,%1,%2,%3},{%4,%5,%6,%7},{%8,%9},{%0,%1,%2,%3};"
                        : "+f"(acc[mi][ni][0]), "+f"(acc[mi][ni][1]),
                          "+f"(acc[mi][ni][2]), "+f"(acc[mi][ni][3])
                        : "r"(a[mi][0]), "r"(a[mi][1]), "r"(a[mi][2]), "r"(a[mi][3]),
                          "r"(bf[ni][0]), "r"(bf[ni][1]));
        }
        if (kt < NT - 1) {
            int nb = buf ^ 1;
            sa [nb][lr][lc+0] = f2tf32(pa.x);  sa [nb][lr][lc+1] = f2tf32(pa.y);
            sa [nb][lr][lc+2] = f2tf32(pa.z);  sa [nb][lr][lc+3] = f2tf32(pa.w);
            sbm[nb][lr][lc+0] = f2tf32(pb0.x); sbm[nb][lr][lc+1] = f2tf32(pb0.y);
            sbm[nb][lr][lc+2] = f2tf32(pb0.z); sbm[nb][lr][lc+3] = f2tf32(pb0.w);
            sbm[nb][lr+64][lc+0] = f2tf32(pb1.x); sbm[nb][lr+64][lc+1] = f2tf32(pb1.y);
            sbm[nb][lr+64][lc+2] = f2tf32(pb1.z); sbm[nb][lr+64][lc+3] = f2tf32(pb1.w);
        }
        __syncthreads();
    }

    #pragma unroll
    for (int mi = 0; mi < 2; mi++)
        #pragma unroll
        for (int ni = 0; ni < 4; ni++) {
            int r0 = mB + mBase + mi * 16 + g;
            int c0 = nB + nBase + ni * 8 + t * 2;
            float bm0 = bm[c0], bm1 = bm[c0 + 1];
            out[(size_t)r0 * FOUT + c0]           = acc[mi][ni][0] + bm0;
            out[(size_t)r0 * FOUT + c0 + 1]       = acc[mi][ni][1] + bm1;
            out[(size_t)(r0 + 8) * FOUT + c0]     = acc[mi][ni][2] + bm0;
            out[(size_t)(r0 + 8) * FOUT + c0 + 1] = acc[mi][ni][3] + bm1;
        }
}

// ---------------------------------------------------------------------------
extern "C" void kernel_launch(void* const* d_in, const int* in_sizes, int n_in,
                              void* d_out, int out_size) {
    const float*         x   = (const float*)d_in[0];
    const unsigned char* xm  = (const unsigned char*)d_in[1];
    const float*         W1  = (const float*)d_in[2];
    const float*         b1  = (const float*)d_in[3];
    const float*         W2  = (const float*)d_in[4];
    // d_in[5] = b2: softmax-invariant, unused
    const float*         Wm  = (const float*)d_in[6];
    const float*         bm  = (const float*)d_in[7];
    const float*         G   = (const float*)d_in[8];
    const float*         mub = (const float*)d_in[9];
    float* out = (float*)d_out;

    k_pre<<<610, 256>>>(W1);
    k_mlp_att<<<dim3(4, ROWS / 128), 256>>>(x, b1, W2);
    k_stats4<<<dim3(4, BATCH), 256>>>(x, xm, G, mub);
    k_out2<<<dim3(BATCH / BM2, FOUT / BN2), 256>>>(Wm, bm, out);
}